// round 1
// baseline (speedup 1.0000x reference)
#include <cuda_runtime.h>

// MaskedCommonWeightSimpleLinearGNN:
//   w = left_weights * A   (A is binary, ~1% dense, 8192x8192)
//   for 3 layers: x = (w @ x) @ W_l^T + b_l
//
// Strategy: build an ELL sparse representation of w ONCE (one warp per row,
// ballot-compaction, reads A fully but gathers left_weights only at nonzeros),
// then run 3 SpMM+linear layers where the 2MB activation matrix is L2-resident.

#define NN   8192
#define DD   64
#define CAP  192      // max nnz/row; Binomial(8192,0.01) mean 82, sigma 9 -> 192 is >12 sigma

// ---- allocation-free scratch (device globals) ----
__device__ int   g_cnt[NN];
__device__ int   g_cols[(size_t)NN * CAP];
__device__ float g_vals[(size_t)NN * CAP];
__device__ float g_buf0[(size_t)NN * DD];
__device__ float g_buf1[(size_t)NN * DD];

// ============================================================================
// Kernel 1: build ELL. One warp per row. Scans A row (float4 per lane),
// ballot-compacts nonzero columns in a fixed deterministic order, and gathers
// left_weights only at those columns.
// ============================================================================
__global__ void build_ell_kernel(const float* __restrict__ A,
                                 const float* __restrict__ LW) {
    int warps_per_block = blockDim.x >> 5;
    int row  = blockIdx.x * warps_per_block + (threadIdx.x >> 5);
    int lane = threadIdx.x & 31;
    if (row >= NN) return;

    const float4* a4  = reinterpret_cast<const float4*>(A + (size_t)row * NN);
    const float*  lw  = LW + (size_t)row * NN;
    int*   cols = g_cols + (size_t)row * CAP;
    float* vals = g_vals + (size_t)row * CAP;

    int cnt = 0;
    // 8192 cols = 64 chunks of 128 cols (32 lanes x float4)
    for (int c = 0; c < NN / 128; ++c) {
        float4 v = a4[c * 32 + lane];
        float a[4] = {v.x, v.y, v.z, v.w};
        #pragma unroll
        for (int r = 0; r < 4; ++r) {
            bool nz = (a[r] != 0.0f);
            unsigned m = __ballot_sync(0xffffffffu, nz);
            if (nz) {
                int pos = cnt + __popc(m & ((1u << lane) - 1u));
                if (pos < CAP) {
                    int col = c * 128 + lane * 4 + r;
                    cols[pos] = col;
                    vals[pos] = lw[col];   // gather LW only where mask is set
                }
            }
            cnt += __popc(m);
        }
    }
    if (lane == 0) g_cnt[row] = (cnt < CAP) ? cnt : CAP;
}

// ============================================================================
// Kernel 2: one layer: out[row,:] = (sum_k vals[row,k] * xin[cols[row,k],:]) @ W^T + b
// 128 threads per block = 2 rows; thread t (0..63) owns output feature t.
// xin is 2MB -> L2-resident, gathers are L2 hits.
// ============================================================================
__global__ void layer_kernel(const float* __restrict__ xin,
                             const float* __restrict__ W,   // [64,64] row-major (out,in)
                             const float* __restrict__ b,   // [64]
                             float* __restrict__ xout) {
    __shared__ float shW[DD * 65];   // padded: bank-conflict-free reads shW[t*65+d]
    __shared__ float shY[2][DD];

    int tid = threadIdx.x;
    // cooperative W load (coalesced global, conflict-free shared stores)
    for (int i = tid; i < DD * DD; i += 128) {
        shW[(i >> 6) * 65 + (i & 63)] = W[i];
    }

    int sub = tid >> 6;             // which of the 2 rows in this block
    int t   = tid & 63;             // feature index
    int row = blockIdx.x * 2 + sub;

    const int*   cols = g_cols + (size_t)row * CAP;
    const float* vals = g_vals + (size_t)row * CAP;
    int cnt = g_cnt[row];

    float acc = 0.0f;
    int k = 0;
    for (; k + 4 <= cnt; k += 4) {
        int   c0 = cols[k], c1 = cols[k + 1], c2 = cols[k + 2], c3 = cols[k + 3];
        float v0 = vals[k], v1 = vals[k + 1], v2 = vals[k + 2], v3 = vals[k + 3];
        float x0 = xin[c0 * DD + t];
        float x1 = xin[c1 * DD + t];
        float x2 = xin[c2 * DD + t];
        float x3 = xin[c3 * DD + t];
        acc += v0 * x0;
        acc += v1 * x1;
        acc += v2 * x2;
        acc += v3 * x3;
    }
    for (; k < cnt; ++k) acc += vals[k] * xin[cols[k] * DD + t];

    shY[sub][t] = acc;
    __syncthreads();

    float z = b[t];
    #pragma unroll
    for (int d = 0; d < DD; ++d)
        z += shY[sub][d] * shW[t * 65 + d];

    xout[(size_t)row * DD + t] = z;
}

// ============================================================================
// Launch
// ============================================================================
extern "C" void kernel_launch(void* const* d_in, const int* in_sizes, int n_in,
                              void* d_out, int out_size) {
    const float* x  = (const float*)d_in[0];   // [8192,64]
    const float* A  = (const float*)d_in[1];   // [8192,8192]
    const float* LW = (const float*)d_in[2];   // [8192,8192]
    const float* W0 = (const float*)d_in[3];
    const float* b0 = (const float*)d_in[4];
    const float* W1 = (const float*)d_in[5];
    const float* b1 = (const float*)d_in[6];
    const float* W2 = (const float*)d_in[7];
    const float* b2 = (const float*)d_in[8];
    float* out = (float*)d_out;

    float* buf0; cudaGetSymbolAddress((void**)&buf0, g_buf0);
    float* buf1; cudaGetSymbolAddress((void**)&buf1, g_buf1);

    // Build ELL: 8 warps/block -> 8 rows/block -> 1024 blocks
    build_ell_kernel<<<NN / 8, 256>>>(A, LW);

    // 3 layers: 2 rows/block -> 4096 blocks of 128 threads
    layer_kernel<<<NN / 2, 128>>>(x,    W0, b0, buf0);
    layer_kernel<<<NN / 2, 128>>>(buf0, W1, b1, buf1);
    layer_kernel<<<NN / 2, 128>>>(buf1, W2, b2, out);
}

// round 2
// speedup vs baseline: 1.2000x; 1.2000x over previous
#include <cuda_runtime.h>

// MaskedCommonWeightSimpleLinearGNN, algebraically refactored:
//   w = LW * A  (binary mask, ~1% dense, 8192x8192), same w all 3 layers.
//   out = w^3 (x M) + (w^2 1) c0^T + (w 1) c1^T + 1 b2^T
//     M  = W0^T W1^T W2^T,  c0 = W2 W1 b0,  c1 = W2 b1
// Pipeline: build ELL (+row sums s1) -> tiny dense preps -> x0 = x M ->
//           s2 = w s1 -> three pure SpMMs (rank-1 epilogue fused in last).

#define NN   8192
#define DD   64
#define CAP  192      // Binomial(8192,0.01): mean 82, sigma 9 -> 192 is huge margin
#define RPB  16       // rows per block in SpMM

// ---- allocation-free scratch ----
__device__ int   g_cnt[NN];
__device__ int   g_cols[(size_t)NN * CAP];
__device__ float g_vals[(size_t)NN * CAP];
__device__ float g_s1[NN];
__device__ float g_s2[NN];
__device__ float g_P[DD * DD];
__device__ float g_M[DD * DD];
__device__ float g_q[DD];
__device__ float g_c0[DD];
__device__ float g_c1[DD];
__device__ float g_buf0[(size_t)NN * DD];
__device__ float g_buf1[(size_t)NN * DD];

// ============================================================================
// 1) Build ELL: one warp per row, double-buffered A scan, ballot compaction,
//    sparse gather of LW, and row-sum s1 on the fly.
// ============================================================================
__global__ void build_ell_kernel(const float* __restrict__ A,
                                 const float* __restrict__ LW) {
    int row  = blockIdx.x * (blockDim.x >> 5) + (threadIdx.x >> 5);
    int lane = threadIdx.x & 31;
    if (row >= NN) return;

    const float4* a4 = reinterpret_cast<const float4*>(A + (size_t)row * NN);
    const float*  lw = LW + (size_t)row * NN;
    int*   cols = g_cols + (size_t)row * CAP;
    float* vals = g_vals + (size_t)row * CAP;

    int   cnt  = 0;
    float ssum = 0.0f;

    float4 cur = a4[lane];                      // prefetch chunk 0
    for (int c = 0; c < NN / 128; ++c) {
        float4 nxt;
        if (c + 1 < NN / 128) nxt = a4[(c + 1) * 32 + lane];  // overlap next load
        float a[4] = {cur.x, cur.y, cur.z, cur.w};
        #pragma unroll
        for (int r = 0; r < 4; ++r) {
            bool nz = (a[r] != 0.0f);
            unsigned m = __ballot_sync(0xffffffffu, nz);
            if (nz) {
                int pos = cnt + __popc(m & ((1u << lane) - 1u));
                if (pos < CAP) {
                    int col = c * 128 + lane * 4 + r;
                    float v = lw[col];
                    cols[pos] = col;
                    vals[pos] = v;
                    ssum += v;
                }
            }
            cnt += __popc(m);
        }
        cur = nxt;
    }
    // warp-reduce row sum
    #pragma unroll
    for (int o = 16; o; o >>= 1) ssum += __shfl_xor_sync(0xffffffffu, ssum, o);
    if (lane == 0) {
        g_cnt[row] = (cnt < CAP) ? cnt : CAP;
        g_s1[row]  = ssum;
    }
}

// ============================================================================
// 2) prep1: P = W0^T W1^T  (P[d,e] = sum_f W0[f,d] W1[e,f]);
//    block 0 also computes q = W1 b0 and c1 = W2 b1.
// ============================================================================
__global__ void prep1_kernel(const float* __restrict__ W0,
                             const float* __restrict__ W1,
                             const float* __restrict__ b0,
                             const float* __restrict__ W2,
                             const float* __restrict__ b1) {
    __shared__ float sW0[DD * DD];
    __shared__ float sW1[DD * DD];
    int tid = threadIdx.x;
    for (int i = tid; i < DD * DD; i += 256) { sW0[i] = W0[i]; sW1[i] = W1[i]; }
    __syncthreads();

    int base = blockIdx.x * 1024;
    for (int j = 0; j < 4; ++j) {
        int idx = base + j * 256 + tid;
        int d = idx >> 6, e = idx & 63;
        float s = 0.0f;
        #pragma unroll
        for (int f = 0; f < DD; ++f) s += sW0[f * DD + d] * sW1[e * DD + f];
        g_P[idx] = s;
    }
    if (blockIdx.x == 0 && tid < DD) {
        float s = 0.0f;
        #pragma unroll
        for (int d = 0; d < DD; ++d) s += sW1[tid * DD + d] * b0[d];
        g_q[tid] = s;
        float s2 = 0.0f;
        #pragma unroll
        for (int d = 0; d < DD; ++d) s2 += W2[tid * DD + d] * b1[d];
        g_c1[tid] = s2;
    }
}

// ============================================================================
// 3) prep2: M[d,t] = sum_e P[d,e] W2[t,e];  block 0: c0 = W2 q.
// ============================================================================
__global__ void prep2_kernel(const float* __restrict__ W2) {
    __shared__ float sP[DD * DD];
    __shared__ float sW2[DD * DD];
    int tid = threadIdx.x;
    for (int i = tid; i < DD * DD; i += 256) { sP[i] = g_P[i]; sW2[i] = W2[i]; }
    __syncthreads();

    int base = blockIdx.x * 1024;
    for (int j = 0; j < 4; ++j) {
        int idx = base + j * 256 + tid;
        int d = idx >> 6, t = idx & 63;
        float s = 0.0f;
        #pragma unroll
        for (int e = 0; e < DD; ++e) s += sP[d * DD + e] * sW2[t * DD + e];
        g_M[idx] = s;
    }
    if (blockIdx.x == 0 && tid < DD) {
        float s = 0.0f;
        #pragma unroll
        for (int e = 0; e < DD; ++e) s += sW2[tid * DD + e] * g_q[e];
        g_c0[tid] = s;
    }
}

// ============================================================================
// 4) x0 = x M   (8192x64 @ 64x64)
// ============================================================================
__global__ void xm_kernel(const float* __restrict__ x, float* __restrict__ x0) {
    __shared__ float sM[DD * DD];
    __shared__ float sX[RPB][DD];
    int tid  = threadIdx.x;
    int row0 = blockIdx.x * RPB;

    for (int i = tid; i < DD * DD; i += 256) sM[i] = g_M[i];
    for (int i = tid; i < RPB * DD; i += 256)
        sX[i >> 6][i & 63] = x[(size_t)(row0 + (i >> 6)) * DD + (i & 63)];
    __syncthreads();

    int r = tid >> 4, l = tid & 15;
    float4 acc = make_float4(0.f, 0.f, 0.f, 0.f);
    #pragma unroll 8
    for (int d = 0; d < DD; ++d) {
        float xd  = sX[r][d];
        float4 m4 = reinterpret_cast<const float4*>(sM + d * DD)[l];
        acc.x += xd * m4.x; acc.y += xd * m4.y;
        acc.z += xd * m4.z; acc.w += xd * m4.w;
    }
    reinterpret_cast<float4*>(x0)[(size_t)(row0 + r) * 16 + l] = acc;
}

// ============================================================================
// 5) s2 = w s1   (warp per row)
// ============================================================================
__global__ void s2_kernel() {
    int row  = blockIdx.x * 4 + (threadIdx.x >> 5);
    int lane = threadIdx.x & 31;
    const int*   cr = g_cols + (size_t)row * CAP;
    const float* vr = g_vals + (size_t)row * CAP;
    int cnt = g_cnt[row];
    float s = 0.0f;
    for (int k = lane; k < cnt; k += 32) s += vr[k] * g_s1[cr[k]];
    #pragma unroll
    for (int o = 16; o; o >>= 1) s += __shfl_xor_sync(0xffffffffu, s, o);
    if (lane == 0) g_s2[row] = s;
}

// ============================================================================
// 6) SpMM: xout = w @ xin  (+ optional rank-1 epilogue on final layer)
//    16 rows/block, 256 threads; cols/vals staged in shared; float4 gathers.
// ============================================================================
__global__ void __launch_bounds__(256)
spmm_kernel(const float* __restrict__ xin, float* __restrict__ xout,
            const float* __restrict__ b2, int final_flag) {
    __shared__ int   sC[RPB * CAP];
    __shared__ float sV[RPB * CAP];
    __shared__ int   sCnt[RPB];

    int tid  = threadIdx.x;
    int row0 = blockIdx.x * RPB;

    if (tid < RPB) sCnt[tid] = g_cnt[row0 + tid];
    const int*   gc = g_cols + (size_t)row0 * CAP;
    const float* gv = g_vals + (size_t)row0 * CAP;
    #pragma unroll
    for (int j = 0; j < (RPB * CAP) / 256; ++j) {
        int i = j * 256 + tid;
        sC[i] = gc[i];
        sV[i] = gv[i];
    }
    __syncthreads();

    int r = tid >> 4, l = tid & 15;
    int cnt = sCnt[r];
    const int*   cr = sC + r * CAP;
    const float* vr = sV + r * CAP;
    const float4* x4 = reinterpret_cast<const float4*>(xin);

    float4 a0 = make_float4(0.f,0.f,0.f,0.f), a1 = a0, a2 = a0, a3 = a0;
    int k = 0;
    for (; k + 4 <= cnt; k += 4) {
        int   c0 = cr[k],  c1 = cr[k+1], c2 = cr[k+2], c3 = cr[k+3];
        float v0 = vr[k],  v1 = vr[k+1], v2 = vr[k+2], v3 = vr[k+3];
        float4 g0 = __ldg(&x4[c0 * 16 + l]);
        float4 g1 = __ldg(&x4[c1 * 16 + l]);
        float4 g2 = __ldg(&x4[c2 * 16 + l]);
        float4 g3 = __ldg(&x4[c3 * 16 + l]);
        a0.x += v0*g0.x; a0.y += v0*g0.y; a0.z += v0*g0.z; a0.w += v0*g0.w;
        a1.x += v1*g1.x; a1.y += v1*g1.y; a1.z += v1*g1.z; a1.w += v1*g1.w;
        a2.x += v2*g2.x; a2.y += v2*g2.y; a2.z += v2*g2.z; a2.w += v2*g2.w;
        a3.x += v3*g3.x; a3.y += v3*g3.y; a3.z += v3*g3.z; a3.w += v3*g3.w;
    }
    for (; k < cnt; ++k) {
        int c = cr[k]; float v = vr[k];
        float4 g = __ldg(&x4[c * 16 + l]);
        a0.x += v*g.x; a0.y += v*g.y; a0.z += v*g.z; a0.w += v*g.w;
    }
    float4 acc;
    acc.x = (a0.x + a1.x) + (a2.x + a3.x);
    acc.y = (a0.y + a1.y) + (a2.y + a3.y);
    acc.z = (a0.z + a1.z) + (a2.z + a3.z);
    acc.w = (a0.w + a1.w) + (a2.w + a3.w);

    if (final_flag) {
        int row = row0 + r;
        float s1v = g_s1[row], s2v = g_s2[row];
        float4 c0v = reinterpret_cast<const float4*>(g_c0)[l];
        float4 c1v = reinterpret_cast<const float4*>(g_c1)[l];
        float4 bv  = __ldg(&reinterpret_cast<const float4*>(b2)[l]);
        acc.x += s2v * c0v.x + s1v * c1v.x + bv.x;
        acc.y += s2v * c0v.y + s1v * c1v.y + bv.y;
        acc.z += s2v * c0v.z + s1v * c1v.z + bv.z;
        acc.w += s2v * c0v.w + s1v * c1v.w + bv.w;
    }
    reinterpret_cast<float4*>(xout)[(size_t)(row0 + r) * 16 + l] = acc;
}

// ============================================================================
// Launch
// ============================================================================
extern "C" void kernel_launch(void* const* d_in, const int* in_sizes, int n_in,
                              void* d_out, int out_size) {
    const float* x  = (const float*)d_in[0];
    const float* A  = (const float*)d_in[1];
    const float* LW = (const float*)d_in[2];
    const float* W0 = (const float*)d_in[3];
    const float* b0 = (const float*)d_in[4];
    const float* W1 = (const float*)d_in[5];
    const float* b1 = (const float*)d_in[6];
    const float* W2 = (const float*)d_in[7];
    const float* b2 = (const float*)d_in[8];
    float* out = (float*)d_out;

    float* buf0; cudaGetSymbolAddress((void**)&buf0, g_buf0);
    float* buf1; cudaGetSymbolAddress((void**)&buf1, g_buf1);

    build_ell_kernel<<<NN / 8, 256>>>(A, LW);            // ELL + s1
    prep1_kernel<<<4, 256>>>(W0, W1, b0, W2, b1);        // P, q, c1
    prep2_kernel<<<4, 256>>>(W2);                        // M, c0
    xm_kernel<<<NN / RPB, 256>>>(x, buf0);               // x0 = x M
    s2_kernel<<<NN / 4, 128>>>();                        // s2 = w s1

    spmm_kernel<<<NN / RPB, 256>>>(buf0, buf1, nullptr, 0);  // y1 = w x0
    spmm_kernel<<<NN / RPB, 256>>>(buf1, buf0, nullptr, 0);  // y2 = w y1
    spmm_kernel<<<NN / RPB, 256>>>(buf0, out,  b2,      1);  // out = w y2 + rank-1s
}